// round 14
// baseline (speedup 1.0000x reference)
#include <cuda_runtime.h>
#include <cuda_bf16.h>
#include <cstdint>
#include <cstddef>

#define NKP 21
#define CH 32
#define BB_ 8
#define HH 96
#define WW 96
#define HWPIX (HH*WW)
#define PW 98
#define PPIX (PW*PW)           /* 9604 */

#define SLABH 8                /* image rows per CTA */
#define HROWS (SLABH+2)
#define HALON (HROWS*PW)       /* 980 */
#define NST_A 62
#define NST_B 49

#define RSTRIDE 80

/* smem layout: f/h overlay rows -1..991 -> offset (r+1)*RSTRIDE */
#define SM_FH   0              /* 993 rows x 80B = 79440 */
#define SM_WA   79440
#define SM_WB   82000          /* 9 x 2560 = 23040 */
#define SM_BA   105040
#define SM_BB   105168
#define SM_WP   105296
#define SMEM_SZ 105424

__device__ uint16_t g_fpad[(size_t)BB_*PPIX*CH];
__device__ float    g_fsum[BB_*HWPIX];

/* ---------------- helpers ---------------- */
__device__ __forceinline__ uint32_t smem_u32(const void* p) {
    uint32_t a;
    asm("{ .reg .u64 t; cvta.to.shared.u64 t, %1; cvt.u32.u64 %0, t; }" : "=r"(a) : "l"(p));
    return a;
}
__device__ __forceinline__ uint64_t pack2(float v) {
    uint64_t r; asm("mov.b64 %0, {%1, %1};" : "=l"(r) : "f"(v)); return r;
}
__device__ __forceinline__ void ffma2(uint64_t& d, uint64_t a, uint64_t b) {
    asm("fma.rn.f32x2 %0, %1, %2, %0;" : "+l"(d) : "l"(a), "l"(b));
}
__device__ __forceinline__ float2 unpack2(uint64_t v) {
    float2 f; asm("mov.b64 {%0, %1}, %2;" : "=f"(f.x), "=f"(f.y) : "l"(v)); return f;
}
__device__ __forceinline__ uint32_t pk_bf16x2(float v0, float v1) {
    uint32_t r; asm("cvt.rn.bf16x2.f32 %0, %1, %2;" : "=r"(r) : "f"(v1), "f"(v0)); return r;
}
__device__ __forceinline__ void ldsm_x4(uint32_t* r, uint32_t addr) {
    asm volatile("ldmatrix.sync.aligned.m8n8.x4.shared.b16 {%0,%1,%2,%3}, [%4];"
                 : "=r"(r[0]), "=r"(r[1]), "=r"(r[2]), "=r"(r[3]) : "r"(addr));
}
__device__ __forceinline__ void mma16816(float* c, const uint32_t* a, const uint32_t* b) {
    asm volatile("mma.sync.aligned.m16n8k16.row.col.f32.bf16.bf16.f32 "
                 "{%0,%1,%2,%3}, {%4,%5,%6,%7}, {%8,%9}, {%0,%1,%2,%3};"
                 : "+f"(c[0]), "+f"(c[1]), "+f"(c[2]), "+f"(c[3])
                 : "r"(a[0]), "r"(a[1]), "r"(a[2]), "r"(a[3]), "r"(b[0]), "r"(b[1]));
}

/* ------------------------------------------------------------------ */
/* Kernel 1: f = relu(x @ w2 + b2) -> g_fpad (bf16, 98x98, zero borders) */
/* ------------------------------------------------------------------ */
__global__ void __launch_bounds__(256)
k1_f(const float* __restrict__ x, const float* __restrict__ w2,
     const float* __restrict__ b2)
{
    __shared__ float w2s[CH*CH];
    __shared__ float b2s[CH];
    int tid = threadIdx.x;
    for (int i = tid; i < CH*CH; i += 256) w2s[i] = w2[i];
    if (tid < CH) b2s[tid] = b2[tid];
    __syncthreads();

    int p = blockIdx.x * 256 + tid;
    if (p >= BB_*PPIX) return;
    int b  = p / PPIX;
    int r  = p % PPIX;
    int py = r / PW, px = r % PW;

    uint4* fr = (uint4*)(g_fpad + (size_t)p * CH);

    if (py == 0 || py == PW-1 || px == 0 || px == PW-1) {
        uint4 z = make_uint4(0,0,0,0);
        fr[0] = z; fr[1] = z; fr[2] = z; fr[3] = z;
        return;
    }
    int y = py - 1, xx = px - 1;

    uint64_t acc[CH/2];
    const uint64_t* b2p = (const uint64_t*)b2s;
#pragma unroll
    for (int j = 0; j < CH/2; j++) acc[j] = b2p[j];

    const float4* xp = (const float4*)(x + ((size_t)(b*HH + y)*WW + xx)*CH);
    const ulonglong2* w2v = (const ulonglong2*)w2s;
#pragma unroll 2
    for (int c4 = 0; c4 < CH/4; c4++) {
        float4 v = xp[c4];
        float vv[4] = {v.x, v.y, v.z, v.w};
#pragma unroll
        for (int k = 0; k < 4; k++) {
            uint64_t hv = pack2(vv[k]);
            int c = c4*4 + k;
#pragma unroll
            for (int j = 0; j < 8; j++) {
                ulonglong2 w = w2v[c*8 + j];
                ffma2(acc[2*j+0], hv, w.x);
                ffma2(acc[2*j+1], hv, w.y);
            }
        }
    }

    float s = 0.f;
    uint32_t pk[16];
#pragma unroll
    for (int j = 0; j < CH/2; j++) {
        float2 a = unpack2(acc[j]);
        float f0 = fmaxf(a.x, 0.f);
        float f1 = fmaxf(a.y, 0.f);
        s += f0 + f1;
        pk[j] = pk_bf16x2(f0, f1);
    }
    fr[0] = make_uint4(pk[0],  pk[1],  pk[2],  pk[3]);
    fr[1] = make_uint4(pk[4],  pk[5],  pk[6],  pk[7]);
    fr[2] = make_uint4(pk[8],  pk[9],  pk[10], pk[11]);
    fr[3] = make_uint4(pk[12], pk[13], pk[14], pk[15]);
    g_fsum[b*HWPIX + y*WW + xx] = s;
}

/* ------------------------------------------------------------------ */
/* Kernel 2: per (keypoint n, batch b, 8-row slab) — mma.sync          */
/* 1 CTA/SM, high-register: 6 strips/warp single pass, taps unrolled   */
/* ------------------------------------------------------------------ */
__global__ void __launch_bounds__(256, 1)
k2_main(const float* __restrict__ wa, const float* __restrict__ ba,
        const float* __restrict__ wb, const float* __restrict__ bb,
        const float* __restrict__ Wp, float* __restrict__ out)
{
    extern __shared__ unsigned char smc[];
    uint32_t sb = smem_u32(smc);

    int tid  = threadIdx.x;
    int wid  = tid >> 5;
    int lane = tid & 31;
    int qid  = lane & 3;
    int row4 = lane >> 2;

    int n   = blockIdx.y / BB_;
    int b   = blockIdx.y % BB_;
    int y0p = blockIdx.x * SLABH;

    /* ---- stage smem ---- */
    {
        const uint4* fsrc = (const uint4*)(g_fpad + ((size_t)b*PPIX + (size_t)y0p*PW) * CH);
        for (int i = tid; i < HALON*4; i += 256) {
            int px = i >> 2, pt = i & 3;
            *(uint4*)(smc + SM_FH + (px+1)*RSTRIDE + pt*16) = fsrc[i];
        }
        if (tid < 65) {
            int s5 = tid / 5, pt = tid % 5;
            int slot = (s5 == 0) ? 0 : (980 + s5);
            *(uint4*)(smc + SM_FH + slot*RSTRIDE + pt*16) = make_uint4(0,0,0,0);
        }
    }
    {
        uint16_t* was = (uint16_t*)(smc + SM_WA);
        for (int i = tid; i < CH*CH; i += 256) {
            int d = i >> 5, c = i & 31;
            __nv_bfloat16 v = __float2bfloat16(wa[n*CH*CH + c*CH + d]);
            was[d*40 + c] = *(uint16_t*)&v;
        }
        uint16_t* wbs = (uint16_t*)(smc + SM_WB);
        for (int i = tid; i < 9*CH*CH; i += 256) {
            int t = i >> 10, r = i & 1023;
            int d = r >> 5, c = r & 31;
            __nv_bfloat16 v = __float2bfloat16(wb[(size_t)n*9*CH*CH + t*CH*CH + c*CH + d]);
            wbs[t*1280 + d*40 + c] = *(uint16_t*)&v;
        }
    }
    if (tid < CH) {
        ((float*)(smc + SM_BA))[tid] = ba[n*CH + tid];
        ((float*)(smc + SM_BB))[tid] = bb[n*CH + tid];
        float s = 0.f;
        const float* wpp = Wp + (n*CH + tid)*CH;
#pragma unroll
        for (int o = 0; o < CH; o++) s += wpp[o];
        ((float*)(smc + SM_WP))[tid] = s;
    }
    __syncthreads();

    uint32_t aoffA  = (uint32_t)(lane & 15) * RSTRIDE + (uint32_t)(lane >> 4) * 16;
    uint32_t aoffB4 = (uint32_t)(lane & 7)  * RSTRIDE + (uint32_t)(lane >> 3) * 16;

    /* ---- stage A: h = relu(f @ wa + ba), in-place over f ---- */
    {
        uint32_t bwa[16];
#pragma unroll
        for (int nb = 0; nb < 4; nb++)
            ldsm_x4(bwa + nb*4, sb + SM_WA + nb*8*RSTRIDE + aoffB4);
        float ba_r[8];
        const float* ba_s = (const float*)(smc + SM_BA);
#pragma unroll
        for (int nb = 0; nb < 4; nb++) {
            ba_r[nb*2+0] = ba_s[nb*8 + qid*2 + 0];
            ba_r[nb*2+1] = ba_s[nb*8 + qid*2 + 1];
        }

        for (int st = wid; st < NST_A; st += 8) {
            int P = st * 16;
            uint32_t abase = sb + SM_FH + (uint32_t)(P+1)*RSTRIDE;
            uint32_t A0[4], A1[4];
            ldsm_x4(A0, abase + aoffA);
            ldsm_x4(A1, abase + 32 + aoffA);

            float acc[16];
#pragma unroll
            for (int i = 0; i < 16; i++) acc[i] = 0.f;
#pragma unroll
            for (int nb = 0; nb < 4; nb++) {
                mma16816(acc + nb*4, A0, bwa + nb*4);
                mma16816(acc + nb*4, A1, bwa + nb*4 + 2);
            }

            int p0 = P + row4, p1 = p0 + 8;
            int px0 = p0 % PW, py0 = y0p + p0 / PW;
            int px1 = p1 % PW, py1 = y0p + p1 / PW;
            bool v0 = (p0 < HALON) && (px0 >= 1) && (px0 <= WW) && (py0 >= 1) && (py0 <= HH);
            bool v1 = (p1 < HALON) && (px1 >= 1) && (px1 <= WW) && (py1 >= 1) && (py1 <= HH);
#pragma unroll
            for (int nb = 0; nb < 4; nb++) {
                float e0 = v0 ? fmaxf(acc[nb*4+0] + ba_r[nb*2+0], 0.f) : 0.f;
                float e1 = v0 ? fmaxf(acc[nb*4+1] + ba_r[nb*2+1], 0.f) : 0.f;
                float e2 = v1 ? fmaxf(acc[nb*4+2] + ba_r[nb*2+0], 0.f) : 0.f;
                float e3 = v1 ? fmaxf(acc[nb*4+3] + ba_r[nb*2+1], 0.f) : 0.f;
                *(uint32_t*)(smc + SM_FH + (p0+1)*RSTRIDE + nb*16 + qid*4) = pk_bf16x2(e0, e1);
                *(uint32_t*)(smc + SM_FH + (p1+1)*RSTRIDE + nb*16 + qid*4) = pk_bf16x2(e2, e3);
            }
        }
    }
    __syncthreads();

    /* ---- stage B: single pass, 6 strips/warp, taps unrolled ---- */
    {
        float bb_r[8], wp_r[8];
        const float* bb_s = (const float*)(smc + SM_BB);
        const float* wp_s = (const float*)(smc + SM_WP);
#pragma unroll
        for (int nb = 0; nb < 4; nb++) {
            bb_r[nb*2+0] = bb_s[nb*8 + qid*2 + 0];
            bb_r[nb*2+1] = bb_s[nb*8 + qid*2 + 1];
            wp_r[nb*2+0] = wp_s[nb*8 + qid*2 + 0];
            wp_r[nb*2+1] = wp_s[nb*8 + qid*2 + 1];
        }

        /* fsum prefetch for this warp's 6 strips */
        float fpre[6][2];
#pragma unroll
        for (int k = 0; k < 6; k++) {
            int P = PW + (wid + k*8) * 16;
            int p0 = P + row4, p1 = p0 + 8;
            int hx0 = p0 % PW, hy0 = p0 / PW;
            int hx1 = p1 % PW, hy1 = p1 / PW;
            fpre[k][0] = (hx0 >= 1 && hx0 <= WW)
                ? g_fsum[(b*HH + (y0p + hy0 - 1))*WW + (hx0 - 1)] : 0.f;
            fpre[k][1] = (hx1 >= 1 && hx1 <= WW)
                ? g_fsum[(b*HH + (y0p + hy1 - 1))*WW + (hx1 - 1)] : 0.f;
        }

        float acc[6][16];
#pragma unroll
        for (int k = 0; k < 6; k++)
#pragma unroll
            for (int i = 0; i < 16; i++) acc[k][i] = 0.f;

#pragma unroll
        for (int tap = 0; tap < 9; tap++) {
            const int s = (tap/3 - 1)*PW + (tap%3 - 1);
            uint32_t wbase = sb + SM_WB + tap*2560;
            uint32_t bw[16];
#pragma unroll
            for (int nb = 0; nb < 4; nb++)
                ldsm_x4(bw + nb*4, wbase + nb*8*RSTRIDE + aoffB4);

#pragma unroll
            for (int k = 0; k < 6; k++) {
                int P = PW + (wid + k*8) * 16;
                uint32_t abase = sb + SM_FH + (uint32_t)(P + s + 1)*RSTRIDE;
                uint32_t A0[4], A1[4];
                ldsm_x4(A0, abase + aoffA);
                ldsm_x4(A1, abase + 32 + aoffA);
#pragma unroll
                for (int nb = 0; nb < 4; nb++) {
                    mma16816(acc[k] + nb*4, A0, bw + nb*4);
                    mma16816(acc[k] + nb*4, A1, bw + nb*4 + 2);
                }
            }
        }

#pragma unroll
        for (int k = 0; k < 6; k++) {
            int P = PW + (wid + k*8) * 16;
            float l0 = 0.f, l1 = 0.f;
#pragma unroll
            for (int nb = 0; nb < 4; nb++) {
                l0 += fmaxf(acc[k][nb*4+0] + bb_r[nb*2+0], 0.f) * wp_r[nb*2+0];
                l0 += fmaxf(acc[k][nb*4+1] + bb_r[nb*2+1], 0.f) * wp_r[nb*2+1];
                l1 += fmaxf(acc[k][nb*4+2] + bb_r[nb*2+0], 0.f) * wp_r[nb*2+0];
                l1 += fmaxf(acc[k][nb*4+3] + bb_r[nb*2+1], 0.f) * wp_r[nb*2+1];
            }
            l0 += __shfl_xor_sync(0xffffffffu, l0, 1);
            l0 += __shfl_xor_sync(0xffffffffu, l0, 2);
            l1 += __shfl_xor_sync(0xffffffffu, l1, 1);
            l1 += __shfl_xor_sync(0xffffffffu, l1, 2);

            if (qid == 0) {
                int p0 = P + row4;
                int hx0 = p0 % PW, hy0 = p0 / PW;
                if (hx0 >= 1 && hx0 <= WW) {
                    int idx = (b*HH + (y0p + hy0 - 1))*WW + (hx0 - 1);
                    out[(size_t)idx*NKP + n] = fpre[k][0] + l0;
                }
                int p1 = p0 + 8;
                int hx1 = p1 % PW, hy1 = p1 / PW;
                if (hx1 >= 1 && hx1 <= WW) {
                    int idx = (b*HH + (y0p + hy1 - 1))*WW + (hx1 - 1);
                    out[(size_t)idx*NKP + n] = fpre[k][1] + l1;
                }
            }
        }

        /* leftover strip 48 (warp 0 only) */
        if (wid == 0) {
            int P = PW + 48 * 16;
            float a4[16];
#pragma unroll
            for (int i = 0; i < 16; i++) a4[i] = 0.f;
#pragma unroll 1
            for (int tap = 0; tap < 9; tap++) {
                int s = (tap/3 - 1)*PW + (tap%3 - 1);
                uint32_t wbase = sb + SM_WB + tap*2560;
                uint32_t abase = sb + SM_FH + (uint32_t)(P + s + 1)*RSTRIDE;
                uint32_t A0[4], A1[4];
                ldsm_x4(A0, abase + aoffA);
                ldsm_x4(A1, abase + 32 + aoffA);
#pragma unroll
                for (int nb = 0; nb < 4; nb++) {
                    uint32_t bw4[4];
                    ldsm_x4(bw4, wbase + nb*8*RSTRIDE + aoffB4);
                    mma16816(a4 + nb*4, A0, bw4);
                    mma16816(a4 + nb*4, A1, bw4 + 2);
                }
            }
            float l0 = 0.f, l1 = 0.f;
#pragma unroll
            for (int nb = 0; nb < 4; nb++) {
                l0 += fmaxf(a4[nb*4+0] + bb_r[nb*2+0], 0.f) * wp_r[nb*2+0];
                l0 += fmaxf(a4[nb*4+1] + bb_r[nb*2+1], 0.f) * wp_r[nb*2+1];
                l1 += fmaxf(a4[nb*4+2] + bb_r[nb*2+0], 0.f) * wp_r[nb*2+0];
                l1 += fmaxf(a4[nb*4+3] + bb_r[nb*2+1], 0.f) * wp_r[nb*2+1];
            }
            l0 += __shfl_xor_sync(0xffffffffu, l0, 1);
            l0 += __shfl_xor_sync(0xffffffffu, l0, 2);
            l1 += __shfl_xor_sync(0xffffffffu, l1, 1);
            l1 += __shfl_xor_sync(0xffffffffu, l1, 2);
            if (qid == 0) {
                int p0 = P + row4;
                int hx0 = p0 % PW, hy0 = p0 / PW;
                if (hx0 >= 1 && hx0 <= WW) {
                    int idx = (b*HH + (y0p + hy0 - 1))*WW + (hx0 - 1);
                    out[(size_t)idx*NKP + n] = g_fsum[idx] + l0;
                }
                int p1 = p0 + 8;
                int hx1 = p1 % PW, hy1 = p1 / PW;
                if (hx1 >= 1 && hx1 <= WW) {
                    int idx = (b*HH + (y0p + hy1 - 1))*WW + (hx1 - 1);
                    out[(size_t)idx*NKP + n] = g_fsum[idx] + l1;
                }
            }
        }
    }
}

/* ------------------------------------------------------------------ */
extern "C" void kernel_launch(void* const* d_in, const int* in_sizes, int n_in,
                              void* d_out, int out_size)
{
    const float* x  = (const float*)d_in[0];
    const float* w2 = (const float*)d_in[1];
    const float* b2 = (const float*)d_in[2];
    const float* wa = (const float*)d_in[3];
    const float* ba = (const float*)d_in[4];
    const float* wb = (const float*)d_in[5];
    const float* bb = (const float*)d_in[6];
    const float* Wp = (const float*)d_in[7];
    float* out = (float*)d_out;

    k1_f<<<(BB_*PPIX + 255)/256, 256>>>(x, w2, b2);

    cudaFuncSetAttribute(k2_main, cudaFuncAttributeMaxDynamicSharedMemorySize, SMEM_SZ);
    dim3 grid(HH/SLABH, NKP*BB_);
    k2_main<<<grid, 256, SMEM_SZ>>>(wa, ba, wb, bb, Wp, out);
}

// round 15
// speedup vs baseline: 1.3290x; 1.3290x over previous
#include <cuda_runtime.h>
#include <cuda_bf16.h>
#include <cstdint>
#include <cstddef>

#define NKP 21
#define CH 32
#define BB_ 8
#define HH 96
#define WW 96
#define HWPIX (HH*WW)
#define PW 98
#define PPIX (PW*PW)           /* 9604 */

#define SLABH 8                /* image rows per CTA */
#define HROWS (SLABH+2)
#define HALON (HROWS*PW)       /* 980 */
#define NST_A 62
#define NST_B 49

#define RSTRIDE 80

/* smem layout: f/h overlay rows -1..991 -> offset (r+1)*RSTRIDE */
#define SM_FH   0              /* 993 rows x 80B = 79440 */
#define SM_WA   79440
#define SM_WB   82000          /* 9 x 2560 = 23040 */
#define SM_BA   105040
#define SM_BB   105168
#define SM_WP   105296
#define SMEM_SZ 105424

__device__ uint16_t g_fpad[(size_t)BB_*PPIX*CH];
__device__ float    g_fsum[BB_*HWPIX];

/* ---------------- helpers ---------------- */
__device__ __forceinline__ uint32_t smem_u32(const void* p) {
    uint32_t a;
    asm("{ .reg .u64 t; cvta.to.shared.u64 t, %1; cvt.u32.u64 %0, t; }" : "=r"(a) : "l"(p));
    return a;
}
__device__ __forceinline__ uint64_t pack2(float v) {
    uint64_t r; asm("mov.b64 %0, {%1, %1};" : "=l"(r) : "f"(v)); return r;
}
__device__ __forceinline__ void ffma2(uint64_t& d, uint64_t a, uint64_t b) {
    asm("fma.rn.f32x2 %0, %1, %2, %0;" : "+l"(d) : "l"(a), "l"(b));
}
__device__ __forceinline__ float2 unpack2(uint64_t v) {
    float2 f; asm("mov.b64 {%0, %1}, %2;" : "=f"(f.x), "=f"(f.y) : "l"(v)); return f;
}
__device__ __forceinline__ uint32_t pk_bf16x2(float v0, float v1) {
    uint32_t r; asm("cvt.rn.bf16x2.f32 %0, %1, %2;" : "=r"(r) : "f"(v1), "f"(v0)); return r;
}
__device__ __forceinline__ void ldsm_x4(uint32_t* r, uint32_t addr) {
    asm volatile("ldmatrix.sync.aligned.m8n8.x4.shared.b16 {%0,%1,%2,%3}, [%4];"
                 : "=r"(r[0]), "=r"(r[1]), "=r"(r[2]), "=r"(r[3]) : "r"(addr));
}
/* NOT volatile: pure register function — lets the compiler schedule MMAs
   around the (volatile) ldsm stream. */
__device__ __forceinline__ void mma16816(float* c, const uint32_t* a, const uint32_t* b) {
    asm("mma.sync.aligned.m16n8k16.row.col.f32.bf16.bf16.f32 "
        "{%0,%1,%2,%3}, {%4,%5,%6,%7}, {%8,%9}, {%0,%1,%2,%3};"
        : "+f"(c[0]), "+f"(c[1]), "+f"(c[2]), "+f"(c[3])
        : "r"(a[0]), "r"(a[1]), "r"(a[2]), "r"(a[3]), "r"(b[0]), "r"(b[1]));
}

/* ------------------------------------------------------------------ */
/* Kernel 1: f = relu(x @ w2 + b2) -> g_fpad (bf16, 98x98, zero borders) */
/* ------------------------------------------------------------------ */
__global__ void __launch_bounds__(256)
k1_f(const float* __restrict__ x, const float* __restrict__ w2,
     const float* __restrict__ b2)
{
    __shared__ float w2s[CH*CH];
    __shared__ float b2s[CH];
    int tid = threadIdx.x;
    for (int i = tid; i < CH*CH; i += 256) w2s[i] = w2[i];
    if (tid < CH) b2s[tid] = b2[tid];
    __syncthreads();

    int p = blockIdx.x * 256 + tid;
    if (p >= BB_*PPIX) return;
    int b  = p / PPIX;
    int r  = p % PPIX;
    int py = r / PW, px = r % PW;

    uint4* fr = (uint4*)(g_fpad + (size_t)p * CH);

    if (py == 0 || py == PW-1 || px == 0 || px == PW-1) {
        uint4 z = make_uint4(0,0,0,0);
        fr[0] = z; fr[1] = z; fr[2] = z; fr[3] = z;
        return;
    }
    int y = py - 1, xx = px - 1;

    uint64_t acc[CH/2];
    const uint64_t* b2p = (const uint64_t*)b2s;
#pragma unroll
    for (int j = 0; j < CH/2; j++) acc[j] = b2p[j];

    const float4* xp = (const float4*)(x + ((size_t)(b*HH + y)*WW + xx)*CH);
    const ulonglong2* w2v = (const ulonglong2*)w2s;
#pragma unroll 2
    for (int c4 = 0; c4 < CH/4; c4++) {
        float4 v = xp[c4];
        float vv[4] = {v.x, v.y, v.z, v.w};
#pragma unroll
        for (int k = 0; k < 4; k++) {
            uint64_t hv = pack2(vv[k]);
            int c = c4*4 + k;
#pragma unroll
            for (int j = 0; j < 8; j++) {
                ulonglong2 w = w2v[c*8 + j];
                ffma2(acc[2*j+0], hv, w.x);
                ffma2(acc[2*j+1], hv, w.y);
            }
        }
    }

    float s = 0.f;
    uint32_t pk[16];
#pragma unroll
    for (int j = 0; j < CH/2; j++) {
        float2 a = unpack2(acc[j]);
        float f0 = fmaxf(a.x, 0.f);
        float f1 = fmaxf(a.y, 0.f);
        s += f0 + f1;
        pk[j] = pk_bf16x2(f0, f1);
    }
    fr[0] = make_uint4(pk[0],  pk[1],  pk[2],  pk[3]);
    fr[1] = make_uint4(pk[4],  pk[5],  pk[6],  pk[7]);
    fr[2] = make_uint4(pk[8],  pk[9],  pk[10], pk[11]);
    fr[3] = make_uint4(pk[12], pk[13], pk[14], pk[15]);
    g_fsum[b*HWPIX + y*WW + xx] = s;
}

/* ------------------------------------------------------------------ */
/* Kernel 2: per (keypoint n, batch b, 8-row slab) — mma.sync          */
/* 2 CTAs/SM; stage B software-pipelined: A double-buffered across     */
/* (tap,k) groups so ldsm->mma RAW is off the critical path            */
/* ------------------------------------------------------------------ */
__global__ void __launch_bounds__(256, 2)
k2_main(const float* __restrict__ wa, const float* __restrict__ ba,
        const float* __restrict__ wb, const float* __restrict__ bb,
        const float* __restrict__ Wp, float* __restrict__ out)
{
    extern __shared__ unsigned char smc[];
    uint32_t sb = smem_u32(smc);

    int tid  = threadIdx.x;
    int wid  = tid >> 5;
    int lane = tid & 31;
    int qid  = lane & 3;
    int row4 = lane >> 2;

    int n   = blockIdx.y / BB_;
    int b   = blockIdx.y % BB_;
    int y0p = blockIdx.x * SLABH;

    /* ---- stage smem ---- */
    {
        const uint4* fsrc = (const uint4*)(g_fpad + ((size_t)b*PPIX + (size_t)y0p*PW) * CH);
        for (int i = tid; i < HALON*4; i += 256) {
            int px = i >> 2, pt = i & 3;
            *(uint4*)(smc + SM_FH + (px+1)*RSTRIDE + pt*16) = fsrc[i];
        }
        if (tid < 65) {
            int s5 = tid / 5, pt = tid % 5;
            int slot = (s5 == 0) ? 0 : (980 + s5);
            *(uint4*)(smc + SM_FH + slot*RSTRIDE + pt*16) = make_uint4(0,0,0,0);
        }
    }
    {
        uint16_t* was = (uint16_t*)(smc + SM_WA);
        for (int i = tid; i < CH*CH; i += 256) {
            int d = i >> 5, c = i & 31;
            __nv_bfloat16 v = __float2bfloat16(wa[n*CH*CH + c*CH + d]);
            was[d*40 + c] = *(uint16_t*)&v;
        }
        uint16_t* wbs = (uint16_t*)(smc + SM_WB);
        for (int i = tid; i < 9*CH*CH; i += 256) {
            int t = i >> 10, r = i & 1023;
            int d = r >> 5, c = r & 31;
            __nv_bfloat16 v = __float2bfloat16(wb[(size_t)n*9*CH*CH + t*CH*CH + c*CH + d]);
            wbs[t*1280 + d*40 + c] = *(uint16_t*)&v;
        }
    }
    if (tid < CH) {
        ((float*)(smc + SM_BA))[tid] = ba[n*CH + tid];
        ((float*)(smc + SM_BB))[tid] = bb[n*CH + tid];
        float s = 0.f;
        const float* wpp = Wp + (n*CH + tid)*CH;
#pragma unroll
        for (int o = 0; o < CH; o++) s += wpp[o];
        ((float*)(smc + SM_WP))[tid] = s;
    }
    __syncthreads();

    uint32_t aoffA  = (uint32_t)(lane & 15) * RSTRIDE + (uint32_t)(lane >> 4) * 16;
    uint32_t aoffB4 = (uint32_t)(lane & 7)  * RSTRIDE + (uint32_t)(lane >> 3) * 16;

    /* ---- stage A: h = relu(f @ wa + ba), in-place over f ---- */
    {
        uint32_t bwa[16];
#pragma unroll
        for (int nb = 0; nb < 4; nb++)
            ldsm_x4(bwa + nb*4, sb + SM_WA + nb*8*RSTRIDE + aoffB4);
        float ba_r[8];
        const float* ba_s = (const float*)(smc + SM_BA);
#pragma unroll
        for (int nb = 0; nb < 4; nb++) {
            ba_r[nb*2+0] = ba_s[nb*8 + qid*2 + 0];
            ba_r[nb*2+1] = ba_s[nb*8 + qid*2 + 1];
        }

        for (int st = wid; st < NST_A; st += 8) {
            int P = st * 16;
            uint32_t abase = sb + SM_FH + (uint32_t)(P+1)*RSTRIDE;
            uint32_t A0[4], A1[4];
            ldsm_x4(A0, abase + aoffA);
            ldsm_x4(A1, abase + 32 + aoffA);

            float acc[16];
#pragma unroll
            for (int i = 0; i < 16; i++) acc[i] = 0.f;
#pragma unroll
            for (int nb = 0; nb < 4; nb++) {
                mma16816(acc + nb*4, A0, bwa + nb*4);
                mma16816(acc + nb*4, A1, bwa + nb*4 + 2);
            }

            int p0 = P + row4, p1 = p0 + 8;
            int px0 = p0 % PW, py0 = y0p + p0 / PW;
            int px1 = p1 % PW, py1 = y0p + p1 / PW;
            bool v0 = (p0 < HALON) && (px0 >= 1) && (px0 <= WW) && (py0 >= 1) && (py0 <= HH);
            bool v1 = (p1 < HALON) && (px1 >= 1) && (px1 <= WW) && (py1 >= 1) && (py1 <= HH);
#pragma unroll
            for (int nb = 0; nb < 4; nb++) {
                float e0 = v0 ? fmaxf(acc[nb*4+0] + ba_r[nb*2+0], 0.f) : 0.f;
                float e1 = v0 ? fmaxf(acc[nb*4+1] + ba_r[nb*2+1], 0.f) : 0.f;
                float e2 = v1 ? fmaxf(acc[nb*4+2] + ba_r[nb*2+0], 0.f) : 0.f;
                float e3 = v1 ? fmaxf(acc[nb*4+3] + ba_r[nb*2+1], 0.f) : 0.f;
                *(uint32_t*)(smc + SM_FH + (p0+1)*RSTRIDE + nb*16 + qid*4) = pk_bf16x2(e0, e1);
                *(uint32_t*)(smc + SM_FH + (p1+1)*RSTRIDE + nb*16 + qid*4) = pk_bf16x2(e2, e3);
            }
        }
    }
    __syncthreads();

    /* ---- stage B: 2 passes x (taps unrolled, 3 strips, A double-buffer) ---- */
    {
#pragma unroll 1
        for (int g = 0; g < 2; g++) {
            float acc[3][16];
#pragma unroll
            for (int k = 0; k < 3; k++)
#pragma unroll
                for (int i = 0; i < 16; i++) acc[k][i] = 0.f;

            /* fsum prefetch (long-latency LDG issued early) */
            float fpre[3][2];
#pragma unroll
            for (int k = 0; k < 3; k++) {
                int P = PW + (wid + g*8 + k*16) * 16;
                int p0 = P + row4, p1 = p0 + 8;
                int hx0 = p0 % PW, hy0 = p0 / PW;
                int hx1 = p1 % PW, hy1 = p1 / PW;
                fpre[k][0] = (hx0 >= 1 && hx0 <= WW)
                    ? g_fsum[(b*HH + (y0p + hy0 - 1))*WW + (hx0 - 1)] : 0.f;
                fpre[k][1] = (hx1 >= 1 && hx1 <= WW)
                    ? g_fsum[(b*HH + (y0p + hy1 - 1))*WW + (hx1 - 1)] : 0.f;
            }

            uint32_t Abuf[2][8];
            /* prologue: A for (tap0, k0); tap0 shift = -PW-1 */
            {
                int P = PW + (wid + g*8) * 16;
                uint32_t abase = sb + SM_FH + (uint32_t)(P - PW - 1 + 1)*RSTRIDE;
                ldsm_x4(Abuf[0],     abase + aoffA);
                ldsm_x4(Abuf[0] + 4, abase + 32 + aoffA);
            }

#pragma unroll
            for (int tap = 0; tap < 9; tap++) {
                uint32_t wbase = sb + SM_WB + tap*2560;
                uint32_t bw[16];
#pragma unroll
                for (int nb = 0; nb < 4; nb++)
                    ldsm_x4(bw + nb*4, wbase + nb*8*RSTRIDE + aoffB4);

#pragma unroll
                for (int k = 0; k < 3; k++) {
                    const int cur = (tap*3 + k) & 1;
                    /* prefetch next (tap,k) group's A before this group's MMAs */
                    if (!(tap == 8 && k == 2)) {
                        const int ntap = (k < 2) ? tap : tap + 1;
                        const int nk   = (k < 2) ? k + 1 : 0;
                        const int ns = (ntap/3 - 1)*PW + (ntap%3 - 1);
                        int P = PW + (wid + g*8 + nk*16) * 16;
                        uint32_t abase = sb + SM_FH + (uint32_t)(P + ns + 1)*RSTRIDE;
                        ldsm_x4(Abuf[cur ^ 1],     abase + aoffA);
                        ldsm_x4(Abuf[cur ^ 1] + 4, abase + 32 + aoffA);
                    }
#pragma unroll
                    for (int nb = 0; nb < 4; nb++) {
                        mma16816(acc[k] + nb*4, Abuf[cur],     bw + nb*4);
                        mma16816(acc[k] + nb*4, Abuf[cur] + 4, bw + nb*4 + 2);
                    }
                }
            }

            /* epilogue (bb/wp loaded here to keep them dead in the main loop) */
            float bb_r[8], wp_r[8];
            const float* bb_s = (const float*)(smc + SM_BB);
            const float* wp_s = (const float*)(smc + SM_WP);
#pragma unroll
            for (int nb = 0; nb < 4; nb++) {
                bb_r[nb*2+0] = bb_s[nb*8 + qid*2 + 0];
                bb_r[nb*2+1] = bb_s[nb*8 + qid*2 + 1];
                wp_r[nb*2+0] = wp_s[nb*8 + qid*2 + 0];
                wp_r[nb*2+1] = wp_s[nb*8 + qid*2 + 1];
            }

#pragma unroll
            for (int k = 0; k < 3; k++) {
                int P = PW + (wid + g*8 + k*16) * 16;
                float l0 = 0.f, l1 = 0.f;
#pragma unroll
                for (int nb = 0; nb < 4; nb++) {
                    l0 += fmaxf(acc[k][nb*4+0] + bb_r[nb*2+0], 0.f) * wp_r[nb*2+0];
                    l0 += fmaxf(acc[k][nb*4+1] + bb_r[nb*2+1], 0.f) * wp_r[nb*2+1];
                    l1 += fmaxf(acc[k][nb*4+2] + bb_r[nb*2+0], 0.f) * wp_r[nb*2+0];
                    l1 += fmaxf(acc[k][nb*4+3] + bb_r[nb*2+1], 0.f) * wp_r[nb*2+1];
                }
                l0 += __shfl_xor_sync(0xffffffffu, l0, 1);
                l0 += __shfl_xor_sync(0xffffffffu, l0, 2);
                l1 += __shfl_xor_sync(0xffffffffu, l1, 1);
                l1 += __shfl_xor_sync(0xffffffffu, l1, 2);

                if (qid == 0) {
                    int p0 = P + row4;
                    int hx0 = p0 % PW, hy0 = p0 / PW;
                    if (hx0 >= 1 && hx0 <= WW) {
                        int idx = (b*HH + (y0p + hy0 - 1))*WW + (hx0 - 1);
                        out[(size_t)idx*NKP + n] = fpre[k][0] + l0;
                    }
                    int p1 = p0 + 8;
                    int hx1 = p1 % PW, hy1 = p1 / PW;
                    if (hx1 >= 1 && hx1 <= WW) {
                        int idx = (b*HH + (y0p + hy1 - 1))*WW + (hx1 - 1);
                        out[(size_t)idx*NKP + n] = fpre[k][1] + l1;
                    }
                }
            }
        }

        /* leftover strip 48 (warp 0 only) */
        if (wid == 0) {
            float bb_r[8], wp_r[8];
            const float* bb_s = (const float*)(smc + SM_BB);
            const float* wp_s = (const float*)(smc + SM_WP);
#pragma unroll
            for (int nb = 0; nb < 4; nb++) {
                bb_r[nb*2+0] = bb_s[nb*8 + qid*2 + 0];
                bb_r[nb*2+1] = bb_s[nb*8 + qid*2 + 1];
                wp_r[nb*2+0] = wp_s[nb*8 + qid*2 + 0];
                wp_r[nb*2+1] = wp_s[nb*8 + qid*2 + 1];
            }
            int P = PW + 48 * 16;
            float a4[16];
#pragma unroll
            for (int i = 0; i < 16; i++) a4[i] = 0.f;
#pragma unroll 1
            for (int tap = 0; tap < 9; tap++) {
                int s = (tap/3 - 1)*PW + (tap%3 - 1);
                uint32_t wbase = sb + SM_WB + tap*2560;
                uint32_t abase = sb + SM_FH + (uint32_t)(P + s + 1)*RSTRIDE;
                uint32_t A0[4], A1[4];
                ldsm_x4(A0, abase + aoffA);
                ldsm_x4(A1, abase + 32 + aoffA);
#pragma unroll
                for (int nb = 0; nb < 4; nb++) {
                    uint32_t bw4[4];
                    ldsm_x4(bw4, wbase + nb*8*RSTRIDE + aoffB4);
                    mma16816(a4 + nb*4, A0, bw4);
                    mma16816(a4 + nb*4, A1, bw4 + 2);
                }
            }
            float l0 = 0.f, l1 = 0.f;
#pragma unroll
            for (int nb = 0; nb < 4; nb++) {
                l0 += fmaxf(a4[nb*4+0] + bb_r[nb*2+0], 0.f) * wp_r[nb*2+0];
                l0 += fmaxf(a4[nb*4+1] + bb_r[nb*2+1], 0.f) * wp_r[nb*2+1];
                l1 += fmaxf(a4[nb*4+2] + bb_r[nb*2+0], 0.f) * wp_r[nb*2+0];
                l1 += fmaxf(a4[nb*4+3] + bb_r[nb*2+1], 0.f) * wp_r[nb*2+1];
            }
            l0 += __shfl_xor_sync(0xffffffffu, l0, 1);
            l0 += __shfl_xor_sync(0xffffffffu, l0, 2);
            l1 += __shfl_xor_sync(0xffffffffu, l1, 1);
            l1 += __shfl_xor_sync(0xffffffffu, l1, 2);
            if (qid == 0) {
                int p0 = P + row4;
                int hx0 = p0 % PW, hy0 = p0 / PW;
                if (hx0 >= 1 && hx0 <= WW) {
                    int idx = (b*HH + (y0p + hy0 - 1))*WW + (hx0 - 1);
                    out[(size_t)idx*NKP + n] = g_fsum[idx] + l0;
                }
                int p1 = p0 + 8;
                int hx1 = p1 % PW, hy1 = p1 / PW;
                if (hx1 >= 1 && hx1 <= WW) {
                    int idx = (b*HH + (y0p + hy1 - 1))*WW + (hx1 - 1);
                    out[(size_t)idx*NKP + n] = g_fsum[idx] + l1;
                }
            }
        }
    }
}

/* ------------------------------------------------------------------ */
extern "C" void kernel_launch(void* const* d_in, const int* in_sizes, int n_in,
                              void* d_out, int out_size)
{
    const float* x  = (const float*)d_in[0];
    const float* w2 = (const float*)d_in[1];
    const float* b2 = (const float*)d_in[2];
    const float* wa = (const float*)d_in[3];
    const float* ba = (const float*)d_in[4];
    const float* wb = (const float*)d_in[5];
    const float* bb = (const float*)d_in[6];
    const float* Wp = (const float*)d_in[7];
    float* out = (float*)d_out;

    k1_f<<<(BB_*PPIX + 255)/256, 256>>>(x, w2, b2);

    cudaFuncSetAttribute(k2_main, cudaFuncAttributeMaxDynamicSharedMemorySize, SMEM_SZ);
    dim3 grid(HH/SLABH, NKP*BB_);
    k2_main<<<grid, 256, SMEM_SZ>>>(wa, ba, wb, bb, Wp, out);
}

// round 16
// speedup vs baseline: 1.3410x; 1.0091x over previous
#include <cuda_runtime.h>
#include <cuda_bf16.h>
#include <cstdint>
#include <cstddef>

#define NKP 21
#define CH 32
#define BB_ 8
#define HH 96
#define WW 96
#define HWPIX (HH*WW)
#define PW 98
#define PPIX (PW*PW)           /* 9604 */

#define SLABH 8                /* image rows per CTA */
#define HROWS (SLABH+2)
#define HALON (HROWS*PW)       /* 980 */
#define NST_A 62
#define NST_B 49

#define RSTRIDE 80

/* smem layout: f/h overlay rows -1..991 -> offset (r+1)*RSTRIDE */
#define SM_FH   0              /* 993 rows x 80B = 79440 */
#define SM_WA   79440
#define SM_WB   82000          /* 9 x 2560 = 23040 */
#define SM_BA   105040
#define SM_BB   105168
#define SM_WP   105296
#define SMEM_SZ 105424

__device__ uint16_t g_fpad[(size_t)BB_*PPIX*CH];
__device__ float    g_fsum[BB_*HWPIX];

/* ---------------- helpers ---------------- */
__device__ __forceinline__ uint32_t smem_u32(const void* p) {
    uint32_t a;
    asm("{ .reg .u64 t; cvta.to.shared.u64 t, %1; cvt.u32.u64 %0, t; }" : "=r"(a) : "l"(p));
    return a;
}
__device__ __forceinline__ uint64_t pack2(float v) {
    uint64_t r; asm("mov.b64 %0, {%1, %1};" : "=l"(r) : "f"(v)); return r;
}
__device__ __forceinline__ void ffma2(uint64_t& d, uint64_t a, uint64_t b) {
    asm("fma.rn.f32x2 %0, %1, %2, %0;" : "+l"(d) : "l"(a), "l"(b));
}
__device__ __forceinline__ float2 unpack2(uint64_t v) {
    float2 f; asm("mov.b64 {%0, %1}, %2;" : "=f"(f.x), "=f"(f.y) : "l"(v)); return f;
}
__device__ __forceinline__ uint32_t pk_bf16x2(float v0, float v1) {
    uint32_t r; asm("cvt.rn.bf16x2.f32 %0, %1, %2;" : "=r"(r) : "f"(v1), "f"(v0)); return r;
}
__device__ __forceinline__ void ldsm_x4(uint32_t* r, uint32_t addr) {
    asm volatile("ldmatrix.sync.aligned.m8n8.x4.shared.b16 {%0,%1,%2,%3}, [%4];"
                 : "=r"(r[0]), "=r"(r[1]), "=r"(r[2]), "=r"(r[3]) : "r"(addr));
}
/* NOT volatile: pure register op — compiler may schedule around ldsm stream */
__device__ __forceinline__ void mma16816(float* c, const uint32_t* a, const uint32_t* b) {
    asm("mma.sync.aligned.m16n8k16.row.col.f32.bf16.bf16.f32 "
        "{%0,%1,%2,%3}, {%4,%5,%6,%7}, {%8,%9}, {%0,%1,%2,%3};"
        : "+f"(c[0]), "+f"(c[1]), "+f"(c[2]), "+f"(c[3])
        : "r"(a[0]), "r"(a[1]), "r"(a[2]), "r"(a[3]), "r"(b[0]), "r"(b[1]));
}

/* h-row channel permutation: channel c -> bf16 position within row.
   c = nb*8 + qid*2 + e  ->  pos = qid*8 + nb*2 + e
   (lets each stage-A fragment lane store one contiguous 16B chunk) */
__device__ __forceinline__ int hpos(int c) {
    return ((c >> 1) & 3) * 8 + (c >> 3) * 2 + (c & 1);
}

/* ------------------------------------------------------------------ */
/* Kernel 1: f = relu(x @ w2 + b2) -> g_fpad (bf16, 98x98, zero borders) */
/* ------------------------------------------------------------------ */
__global__ void __launch_bounds__(256)
k1_f(const float* __restrict__ x, const float* __restrict__ w2,
     const float* __restrict__ b2)
{
    __shared__ float w2s[CH*CH];
    __shared__ float b2s[CH];
    int tid = threadIdx.x;
    for (int i = tid; i < CH*CH; i += 256) w2s[i] = w2[i];
    if (tid < CH) b2s[tid] = b2[tid];
    __syncthreads();

    int p = blockIdx.x * 256 + tid;
    if (p >= BB_*PPIX) return;
    int b  = p / PPIX;
    int r  = p % PPIX;
    int py = r / PW, px = r % PW;

    uint4* fr = (uint4*)(g_fpad + (size_t)p * CH);

    if (py == 0 || py == PW-1 || px == 0 || px == PW-1) {
        uint4 z = make_uint4(0,0,0,0);
        fr[0] = z; fr[1] = z; fr[2] = z; fr[3] = z;
        return;
    }
    int y = py - 1, xx = px - 1;

    uint64_t acc[CH/2];
    const uint64_t* b2p = (const uint64_t*)b2s;
#pragma unroll
    for (int j = 0; j < CH/2; j++) acc[j] = b2p[j];

    const float4* xp = (const float4*)(x + ((size_t)(b*HH + y)*WW + xx)*CH);
    const ulonglong2* w2v = (const ulonglong2*)w2s;
#pragma unroll 2
    for (int c4 = 0; c4 < CH/4; c4++) {
        float4 v = xp[c4];
        float vv[4] = {v.x, v.y, v.z, v.w};
#pragma unroll
        for (int k = 0; k < 4; k++) {
            uint64_t hv = pack2(vv[k]);
            int c = c4*4 + k;
#pragma unroll
            for (int j = 0; j < 8; j++) {
                ulonglong2 w = w2v[c*8 + j];
                ffma2(acc[2*j+0], hv, w.x);
                ffma2(acc[2*j+1], hv, w.y);
            }
        }
    }

    float s = 0.f;
    uint32_t pk[16];
#pragma unroll
    for (int j = 0; j < CH/2; j++) {
        float2 a = unpack2(acc[j]);
        float f0 = fmaxf(a.x, 0.f);
        float f1 = fmaxf(a.y, 0.f);
        s += f0 + f1;
        pk[j] = pk_bf16x2(f0, f1);
    }
    fr[0] = make_uint4(pk[0],  pk[1],  pk[2],  pk[3]);
    fr[1] = make_uint4(pk[4],  pk[5],  pk[6],  pk[7]);
    fr[2] = make_uint4(pk[8],  pk[9],  pk[10], pk[11]);
    fr[3] = make_uint4(pk[12], pk[13], pk[14], pk[15]);
    g_fsum[b*HWPIX + y*WW + xx] = s;
}

/* ------------------------------------------------------------------ */
/* Kernel 2: per (keypoint n, batch b, 8-row slab) — mma.sync          */
/* 2 CTAs/SM; permuted h layout -> STS.128 stage-A epilogue;           */
/* stage B A-double-buffered, taps unrolled                            */
/* ------------------------------------------------------------------ */
__global__ void __launch_bounds__(256, 2)
k2_main(const float* __restrict__ wa, const float* __restrict__ ba,
        const float* __restrict__ wb, const float* __restrict__ bb,
        const float* __restrict__ Wp, float* __restrict__ out)
{
    extern __shared__ unsigned char smc[];
    uint32_t sb = smem_u32(smc);

    int tid  = threadIdx.x;
    int wid  = tid >> 5;
    int lane = tid & 31;
    int qid  = lane & 3;
    int row4 = lane >> 2;

    int n   = blockIdx.y / BB_;
    int b   = blockIdx.y % BB_;
    int y0p = blockIdx.x * SLABH;

    /* ---- stage smem ---- */
    {
        const uint4* fsrc = (const uint4*)(g_fpad + ((size_t)b*PPIX + (size_t)y0p*PW) * CH);
        for (int i = tid; i < HALON*4; i += 256) {
            int px = i >> 2, pt = i & 3;
            *(uint4*)(smc + SM_FH + (px+1)*RSTRIDE + pt*16) = fsrc[i];
        }
        if (tid < 65) {
            int s5 = tid / 5, pt = tid % 5;
            int slot = (s5 == 0) ? 0 : (980 + s5);
            *(uint4*)(smc + SM_FH + slot*RSTRIDE + pt*16) = make_uint4(0,0,0,0);
        }
    }
    {
        /* wa: stage-A B operand — TRUE channel order (matches f layout) */
        uint16_t* was = (uint16_t*)(smc + SM_WA);
        for (int i = tid; i < CH*CH; i += 256) {
            int d = i >> 5, c = i & 31;
            __nv_bfloat16 v = __float2bfloat16(wa[n*CH*CH + c*CH + d]);
            was[d*40 + c] = *(uint16_t*)&v;
        }
        /* wb: stage-B B operand — K columns in h's PERMUTED position order */
        uint16_t* wbs = (uint16_t*)(smc + SM_WB);
        for (int i = tid; i < 9*CH*CH; i += 256) {
            int t = i >> 10, r = i & 1023;
            int d = r >> 5, c = r & 31;
            __nv_bfloat16 v = __float2bfloat16(wb[(size_t)n*9*CH*CH + t*CH*CH + c*CH + d]);
            wbs[t*1280 + d*40 + hpos(c)] = *(uint16_t*)&v;
        }
    }
    if (tid < CH) {
        ((float*)(smc + SM_BA))[tid] = ba[n*CH + tid];
        ((float*)(smc + SM_BB))[tid] = bb[n*CH + tid];
        float s = 0.f;
        const float* wpp = Wp + (n*CH + tid)*CH;
#pragma unroll
        for (int o = 0; o < CH; o++) s += wpp[o];
        ((float*)(smc + SM_WP))[tid] = s;
    }
    __syncthreads();

    uint32_t aoffA  = (uint32_t)(lane & 15) * RSTRIDE + (uint32_t)(lane >> 4) * 16;
    uint32_t aoffB4 = (uint32_t)(lane & 7)  * RSTRIDE + (uint32_t)(lane >> 3) * 16;

    /* ---- stage A: h = relu(f @ wa + ba), in-place, permuted row layout ---- */
    {
        uint32_t bwa[16];
#pragma unroll
        for (int nb = 0; nb < 4; nb++)
            ldsm_x4(bwa + nb*4, sb + SM_WA + nb*8*RSTRIDE + aoffB4);
        float ba_r[8];
        const float* ba_s = (const float*)(smc + SM_BA);
#pragma unroll
        for (int nb = 0; nb < 4; nb++) {
            ba_r[nb*2+0] = ba_s[nb*8 + qid*2 + 0];
            ba_r[nb*2+1] = ba_s[nb*8 + qid*2 + 1];
        }

        for (int st = wid; st < NST_A; st += 8) {
            int P = st * 16;
            uint32_t abase = sb + SM_FH + (uint32_t)(P+1)*RSTRIDE;
            uint32_t A0[4], A1[4];
            ldsm_x4(A0, abase + aoffA);
            ldsm_x4(A1, abase + 32 + aoffA);

            float acc[16];
#pragma unroll
            for (int i = 0; i < 16; i++) acc[i] = 0.f;
#pragma unroll
            for (int nb = 0; nb < 4; nb++) {
                mma16816(acc + nb*4, A0, bwa + nb*4);
                mma16816(acc + nb*4, A1, bwa + nb*4 + 2);
            }

            int p0 = P + row4, p1 = p0 + 8;
            int px0 = p0 % PW, py0 = y0p + p0 / PW;
            int px1 = p1 % PW, py1 = y0p + p1 / PW;
            bool v0 = (p0 < HALON) && (px0 >= 1) && (px0 <= WW) && (py0 >= 1) && (py0 <= HH);
            bool v1 = (p1 < HALON) && (px1 >= 1) && (px1 <= WW) && (py1 >= 1) && (py1 <= HH);

            uint4 q0, q1;
            {
                float e;
                e = v0 ? 1.f : 0.f;  /* predicated pack below via select */
                q0.x = pk_bf16x2(v0 ? fmaxf(acc[0]  + ba_r[0], 0.f) : 0.f,
                                 v0 ? fmaxf(acc[1]  + ba_r[1], 0.f) : 0.f);
                q0.y = pk_bf16x2(v0 ? fmaxf(acc[4]  + ba_r[2], 0.f) : 0.f,
                                 v0 ? fmaxf(acc[5]  + ba_r[3], 0.f) : 0.f);
                q0.z = pk_bf16x2(v0 ? fmaxf(acc[8]  + ba_r[4], 0.f) : 0.f,
                                 v0 ? fmaxf(acc[9]  + ba_r[5], 0.f) : 0.f);
                q0.w = pk_bf16x2(v0 ? fmaxf(acc[12] + ba_r[6], 0.f) : 0.f,
                                 v0 ? fmaxf(acc[13] + ba_r[7], 0.f) : 0.f);
                q1.x = pk_bf16x2(v1 ? fmaxf(acc[2]  + ba_r[0], 0.f) : 0.f,
                                 v1 ? fmaxf(acc[3]  + ba_r[1], 0.f) : 0.f);
                q1.y = pk_bf16x2(v1 ? fmaxf(acc[6]  + ba_r[2], 0.f) : 0.f,
                                 v1 ? fmaxf(acc[7]  + ba_r[3], 0.f) : 0.f);
                q1.z = pk_bf16x2(v1 ? fmaxf(acc[10] + ba_r[4], 0.f) : 0.f,
                                 v1 ? fmaxf(acc[11] + ba_r[5], 0.f) : 0.f);
                q1.w = pk_bf16x2(v1 ? fmaxf(acc[14] + ba_r[6], 0.f) : 0.f,
                                 v1 ? fmaxf(acc[15] + ba_r[7], 0.f) : 0.f);
                (void)e;
            }
            /* permuted layout: lane's chunk at byte qid*16, nb-minor */
            *(uint4*)(smc + SM_FH + (p0+1)*RSTRIDE + qid*16) = q0;
            *(uint4*)(smc + SM_FH + (p1+1)*RSTRIDE + qid*16) = q1;
        }
    }
    __syncthreads();

    /* ---- stage B: 2 passes x (taps unrolled, 3 strips, A double-buffer) ---- */
    {
#pragma unroll 1
        for (int g = 0; g < 2; g++) {
            float acc[3][16];
#pragma unroll
            for (int k = 0; k < 3; k++)
#pragma unroll
                for (int i = 0; i < 16; i++) acc[k][i] = 0.f;

            float fpre[3][2];
#pragma unroll
            for (int k = 0; k < 3; k++) {
                int P = PW + (wid + g*8 + k*16) * 16;
                int p0 = P + row4, p1 = p0 + 8;
                int hx0 = p0 % PW, hy0 = p0 / PW;
                int hx1 = p1 % PW, hy1 = p1 / PW;
                fpre[k][0] = (hx0 >= 1 && hx0 <= WW)
                    ? g_fsum[(b*HH + (y0p + hy0 - 1))*WW + (hx0 - 1)] : 0.f;
                fpre[k][1] = (hx1 >= 1 && hx1 <= WW)
                    ? g_fsum[(b*HH + (y0p + hy1 - 1))*WW + (hx1 - 1)] : 0.f;
            }

            uint32_t Abuf[2][8];
            {
                int P = PW + (wid + g*8) * 16;
                uint32_t abase = sb + SM_FH + (uint32_t)(P - PW - 1 + 1)*RSTRIDE;
                ldsm_x4(Abuf[0],     abase + aoffA);
                ldsm_x4(Abuf[0] + 4, abase + 32 + aoffA);
            }

#pragma unroll
            for (int tap = 0; tap < 9; tap++) {
                uint32_t wbase = sb + SM_WB + tap*2560;
                uint32_t bw[16];
#pragma unroll
                for (int nb = 0; nb < 4; nb++)
                    ldsm_x4(bw + nb*4, wbase + nb*8*RSTRIDE + aoffB4);

#pragma unroll
                for (int k = 0; k < 3; k++) {
                    const int cur = (tap*3 + k) & 1;
                    if (!(tap == 8 && k == 2)) {
                        const int ntap = (k < 2) ? tap : tap + 1;
                        const int nk   = (k < 2) ? k + 1 : 0;
                        const int ns = (ntap/3 - 1)*PW + (ntap%3 - 1);
                        int P = PW + (wid + g*8 + nk*16) * 16;
                        uint32_t abase = sb + SM_FH + (uint32_t)(P + ns + 1)*RSTRIDE;
                        ldsm_x4(Abuf[cur ^ 1],     abase + aoffA);
                        ldsm_x4(Abuf[cur ^ 1] + 4, abase + 32 + aoffA);
                    }
#pragma unroll
                    for (int nb = 0; nb < 4; nb++) {
                        mma16816(acc[k] + nb*4, Abuf[cur],     bw + nb*4);
                        mma16816(acc[k] + nb*4, Abuf[cur] + 4, bw + nb*4 + 2);
                    }
                }
            }

            float bb_r[8], wp_r[8];
            const float* bb_s = (const float*)(smc + SM_BB);
            const float* wp_s = (const float*)(smc + SM_WP);
#pragma unroll
            for (int nb = 0; nb < 4; nb++) {
                bb_r[nb*2+0] = bb_s[nb*8 + qid*2 + 0];
                bb_r[nb*2+1] = bb_s[nb*8 + qid*2 + 1];
                wp_r[nb*2+0] = wp_s[nb*8 + qid*2 + 0];
                wp_r[nb*2+1] = wp_s[nb*8 + qid*2 + 1];
            }

#pragma unroll
            for (int k = 0; k < 3; k++) {
                int P = PW + (wid + g*8 + k*16) * 16;
                float l0 = 0.f, l1 = 0.f;
#pragma unroll
                for (int nb = 0; nb < 4; nb++) {
                    l0 += fmaxf(acc[k][nb*4+0] + bb_r[nb*2+0], 0.f) * wp_r[nb*2+0];
                    l0 += fmaxf(acc[k][nb*4+1] + bb_r[nb*2+1], 0.f) * wp_r[nb*2+1];
                    l1 += fmaxf(acc[k][nb*4+2] + bb_r[nb*2+0], 0.f) * wp_r[nb*2+0];
                    l1 += fmaxf(acc[k][nb*4+3] + bb_r[nb*2+1], 0.f) * wp_r[nb*2+1];
                }
                l0 += __shfl_xor_sync(0xffffffffu, l0, 1);
                l0 += __shfl_xor_sync(0xffffffffu, l0, 2);
                l1 += __shfl_xor_sync(0xffffffffu, l1, 1);
                l1 += __shfl_xor_sync(0xffffffffu, l1, 2);

                if (qid == 0) {
                    int p0 = P + row4;
                    int hx0 = p0 % PW, hy0 = p0 / PW;
                    if (hx0 >= 1 && hx0 <= WW) {
                        int idx = (b*HH + (y0p + hy0 - 1))*WW + (hx0 - 1);
                        out[(size_t)idx*NKP + n] = fpre[k][0] + l0;
                    }
                    int p1 = p0 + 8;
                    int hx1 = p1 % PW, hy1 = p1 / PW;
                    if (hx1 >= 1 && hx1 <= WW) {
                        int idx = (b*HH + (y0p + hy1 - 1))*WW + (hx1 - 1);
                        out[(size_t)idx*NKP + n] = fpre[k][1] + l1;
                    }
                }
            }
        }

        /* leftover strip 48 (warp 0 only) */
        if (wid == 0) {
            float bb_r[8], wp_r[8];
            const float* bb_s = (const float*)(smc + SM_BB);
            const float* wp_s = (const float*)(smc + SM_WP);
#pragma unroll
            for (int nb = 0; nb < 4; nb++) {
                bb_r[nb*2+0] = bb_s[nb*8 + qid*2 + 0];
                bb_r[nb*2+1] = bb_s[nb*8 + qid*2 + 1];
                wp_r[nb*2+0] = wp_s[nb*8 + qid*2 + 0];
                wp_r[nb*2+1] = wp_s[nb*8 + qid*2 + 1];
            }
            int P = PW + 48 * 16;
            float a4[16];
#pragma unroll
            for (int i = 0; i < 16; i++) a4[i] = 0.f;
#pragma unroll 1
            for (int tap = 0; tap < 9; tap++) {
                int s = (tap/3 - 1)*PW + (tap%3 - 1);
                uint32_t wbase = sb + SM_WB + tap*2560;
                uint32_t abase = sb + SM_FH + (uint32_t)(P + s + 1)*RSTRIDE;
                uint32_t A0[4], A1[4];
                ldsm_x4(A0, abase + aoffA);
                ldsm_x4(A1, abase + 32 + aoffA);
#pragma unroll
                for (int nb = 0; nb < 4; nb++) {
                    uint32_t bw4[4];
                    ldsm_x4(bw4, wbase + nb*8*RSTRIDE + aoffB4);
                    mma16816(a4 + nb*4, A0, bw4);
                    mma16816(a4 + nb*4, A1, bw4 + 2);
                }
            }
            float l0 = 0.f, l1 = 0.f;
#pragma unroll
            for (int nb = 0; nb < 4; nb++) {
                l0 += fmaxf(a4[nb*4+0] + bb_r[nb*2+0], 0.f) * wp_r[nb*2+0];
                l0 += fmaxf(a4[nb*4+1] + bb_r[nb*2+1], 0.f) * wp_r[nb*2+1];
                l1 += fmaxf(a4[nb*4+2] + bb_r[nb*2+0], 0.f) * wp_r[nb*2+0];
                l1 += fmaxf(a4[nb*4+3] + bb_r[nb*2+1], 0.f) * wp_r[nb*2+1];
            }
            l0 += __shfl_xor_sync(0xffffffffu, l0, 1);
            l0 += __shfl_xor_sync(0xffffffffu, l0, 2);
            l1 += __shfl_xor_sync(0xffffffffu, l1, 1);
            l1 += __shfl_xor_sync(0xffffffffu, l1, 2);
            if (qid == 0) {
                int p0 = P + row4;
                int hx0 = p0 % PW, hy0 = p0 / PW;
                if (hx0 >= 1 && hx0 <= WW) {
                    int idx = (b*HH + (y0p + hy0 - 1))*WW + (hx0 - 1);
                    out[(size_t)idx*NKP + n] = g_fsum[idx] + l0;
                }
                int p1 = p0 + 8;
                int hx1 = p1 % PW, hy1 = p1 / PW;
                if (hx1 >= 1 && hx1 <= WW) {
                    int idx = (b*HH + (y0p + hy1 - 1))*WW + (hx1 - 1);
                    out[(size_t)idx*NKP + n] = g_fsum[idx] + l1;
                }
            }
        }
    }
}

/* ------------------------------------------------------------------ */
extern "C" void kernel_launch(void* const* d_in, const int* in_sizes, int n_in,
                              void* d_out, int out_size)
{
    const float* x  = (const float*)d_in[0];
    const float* w2 = (const float*)d_in[1];
    const float* b2 = (const float*)d_in[2];
    const float* wa = (const float*)d_in[3];
    const float* ba = (const float*)d_in[4];
    const float* wb = (const float*)d_in[5];
    const float* bb = (const float*)d_in[6];
    const float* Wp = (const float*)d_in[7];
    float* out = (float*)d_out;

    k1_f<<<(BB_*PPIX + 255)/256, 256>>>(x, w2, b2);

    cudaFuncSetAttribute(k2_main, cudaFuncAttributeMaxDynamicSharedMemorySize, SMEM_SZ);
    dim3 grid(HH/SLABH, NKP*BB_);
    k2_main<<<grid, 256, SMEM_SZ>>>(wa, ba, wb, bb, Wp, out);
}

// round 17
// speedup vs baseline: 1.3624x; 1.0160x over previous
#include <cuda_runtime.h>
#include <cuda_bf16.h>
#include <cstdint>
#include <cstddef>

#define NKP 21
#define CH 32
#define BB_ 8
#define HH 96
#define WW 96
#define HWPIX (HH*WW)
#define PW 98
#define PPIX (PW*PW)           /* 9604 */

#define SLABH 8                /* image rows per CTA */
#define HROWS (SLABH+2)
#define HALON (HROWS*PW)       /* 980 */
#define NST_A 62
#define NST_B 49

#define RSTRIDE 80

/* smem layout: f/h overlay rows -1..991 -> offset (r+1)*RSTRIDE */
#define SM_FH   0              /* 993 rows x 80B = 79440 */
#define SM_WA   79440
#define SM_WB   82000          /* 9 x 2560 = 23040 */
#define SM_BA   105040
#define SM_BB   105168
#define SM_WP   105296
#define SMEM_SZ 105424

__device__ uint16_t g_fpad[(size_t)BB_*PPIX*CH];
__device__ float    g_fsum[BB_*HWPIX];
__device__ float    g_scratch[(size_t)NKP*BB_*HWPIX];   /* [n][b*HW] coalesced k2 output */

/* ---------------- helpers ---------------- */
__device__ __forceinline__ uint32_t smem_u32(const void* p) {
    uint32_t a;
    asm("{ .reg .u64 t; cvta.to.shared.u64 t, %1; cvt.u32.u64 %0, t; }" : "=r"(a) : "l"(p));
    return a;
}
__device__ __forceinline__ uint64_t pack2(float v) {
    uint64_t r; asm("mov.b64 %0, {%1, %1};" : "=l"(r) : "f"(v)); return r;
}
__device__ __forceinline__ void ffma2(uint64_t& d, uint64_t a, uint64_t b) {
    asm("fma.rn.f32x2 %0, %1, %2, %0;" : "+l"(d) : "l"(a), "l"(b));
}
__device__ __forceinline__ float2 unpack2(uint64_t v) {
    float2 f; asm("mov.b64 {%0, %1}, %2;" : "=f"(f.x), "=f"(f.y) : "l"(v)); return f;
}
__device__ __forceinline__ uint32_t pk_bf16x2(float v0, float v1) {
    uint32_t r; asm("cvt.rn.bf16x2.f32 %0, %1, %2;" : "=r"(r) : "f"(v1), "f"(v0)); return r;
}
__device__ __forceinline__ void ldsm_x4(uint32_t* r, uint32_t addr) {
    asm volatile("ldmatrix.sync.aligned.m8n8.x4.shared.b16 {%0,%1,%2,%3}, [%4];"
                 : "=r"(r[0]), "=r"(r[1]), "=r"(r[2]), "=r"(r[3]) : "r"(addr));
}
__device__ __forceinline__ void mma16816(float* c, const uint32_t* a, const uint32_t* b) {
    asm("mma.sync.aligned.m16n8k16.row.col.f32.bf16.bf16.f32 "
        "{%0,%1,%2,%3}, {%4,%5,%6,%7}, {%8,%9}, {%0,%1,%2,%3};"
        : "+f"(c[0]), "+f"(c[1]), "+f"(c[2]), "+f"(c[3])
        : "r"(a[0]), "r"(a[1]), "r"(a[2]), "r"(a[3]), "r"(b[0]), "r"(b[1]));
}
__device__ __forceinline__ void cp16(uint32_t saddr, const void* gaddr) {
    asm volatile("cp.async.cg.shared.global [%0], [%1], 16;"
                 :: "r"(saddr), "l"(gaddr) : "memory");
}
__device__ __forceinline__ void cp_wait_all() {
    asm volatile("cp.async.commit_group;\n\tcp.async.wait_group 0;" ::: "memory");
}

/* h-row channel permutation: c = nb*8+qid*2+e -> pos = qid*8+nb*2+e */
__device__ __forceinline__ int hpos(int c) {
    return ((c >> 1) & 3) * 8 + (c >> 3) * 2 + (c & 1);
}

/* ------------------------------------------------------------------ */
/* Kernel 1: f = relu(x @ w2 + b2) -> g_fpad (bf16, 98x98, zero borders) */
/* ------------------------------------------------------------------ */
__global__ void __launch_bounds__(256)
k1_f(const float* __restrict__ x, const float* __restrict__ w2,
     const float* __restrict__ b2)
{
    __shared__ float w2s[CH*CH];
    __shared__ float b2s[CH];
    int tid = threadIdx.x;
    for (int i = tid; i < CH*CH; i += 256) w2s[i] = w2[i];
    if (tid < CH) b2s[tid] = b2[tid];
    __syncthreads();

    int p = blockIdx.x * 256 + tid;
    if (p >= BB_*PPIX) return;
    int b  = p / PPIX;
    int r  = p % PPIX;
    int py = r / PW, px = r % PW;

    uint4* fr = (uint4*)(g_fpad + (size_t)p * CH);

    if (py == 0 || py == PW-1 || px == 0 || px == PW-1) {
        uint4 z = make_uint4(0,0,0,0);
        fr[0] = z; fr[1] = z; fr[2] = z; fr[3] = z;
        return;
    }
    int y = py - 1, xx = px - 1;

    uint64_t acc[CH/2];
    const uint64_t* b2p = (const uint64_t*)b2s;
#pragma unroll
    for (int j = 0; j < CH/2; j++) acc[j] = b2p[j];

    const float4* xp = (const float4*)(x + ((size_t)(b*HH + y)*WW + xx)*CH);
    const ulonglong2* w2v = (const ulonglong2*)w2s;
#pragma unroll 2
    for (int c4 = 0; c4 < CH/4; c4++) {
        float4 v = xp[c4];
        float vv[4] = {v.x, v.y, v.z, v.w};
#pragma unroll
        for (int k = 0; k < 4; k++) {
            uint64_t hv = pack2(vv[k]);
            int c = c4*4 + k;
#pragma unroll
            for (int j = 0; j < 8; j++) {
                ulonglong2 w = w2v[c*8 + j];
                ffma2(acc[2*j+0], hv, w.x);
                ffma2(acc[2*j+1], hv, w.y);
            }
        }
    }

    float s = 0.f;
    uint32_t pk[16];
#pragma unroll
    for (int j = 0; j < CH/2; j++) {
        float2 a = unpack2(acc[j]);
        float f0 = fmaxf(a.x, 0.f);
        float f1 = fmaxf(a.y, 0.f);
        s += f0 + f1;
        pk[j] = pk_bf16x2(f0, f1);
    }
    fr[0] = make_uint4(pk[0],  pk[1],  pk[2],  pk[3]);
    fr[1] = make_uint4(pk[4],  pk[5],  pk[6],  pk[7]);
    fr[2] = make_uint4(pk[8],  pk[9],  pk[10], pk[11]);
    fr[3] = make_uint4(pk[12], pk[13], pk[14], pk[15]);
    g_fsum[b*HWPIX + y*WW + xx] = s;
}

/* ------------------------------------------------------------------ */
/* Kernel 2: per (keypoint n, batch b, 8-row slab) — mma.sync          */
/* cp.async f staging; coalesced scratch output                        */
/* ------------------------------------------------------------------ */
__global__ void __launch_bounds__(256, 2)
k2_main(const float* __restrict__ wa, const float* __restrict__ ba,
        const float* __restrict__ wb, const float* __restrict__ bb,
        const float* __restrict__ Wp)
{
    extern __shared__ unsigned char smc[];
    uint32_t sb = smem_u32(smc);

    int tid  = threadIdx.x;
    int wid  = tid >> 5;
    int lane = tid & 31;
    int qid  = lane & 3;
    int row4 = lane >> 2;

    int n   = blockIdx.y / BB_;
    int b   = blockIdx.y % BB_;
    int y0p = blockIdx.x * SLABH;

    float* scr = g_scratch + (size_t)n * (BB_*HWPIX);

    /* ---- stage f via cp.async (no register round-trip) ---- */
    {
        const uint4* fsrc = (const uint4*)(g_fpad + ((size_t)b*PPIX + (size_t)y0p*PW) * CH);
        for (int i = tid; i < HALON*4; i += 256) {
            int px = i >> 2, pt = i & 3;
            cp16(sb + SM_FH + (px+1)*RSTRIDE + pt*16, fsrc + i);
        }
        if (tid < 65) {
            int s5 = tid / 5, pt = tid % 5;
            int slot = (s5 == 0) ? 0 : (980 + s5);
            *(uint4*)(smc + SM_FH + slot*RSTRIDE + pt*16) = make_uint4(0,0,0,0);
        }
    }
    {
        /* wa: stage-A B operand — TRUE channel order */
        uint16_t* was = (uint16_t*)(smc + SM_WA);
        for (int i = tid; i < CH*CH; i += 256) {
            int d = i >> 5, c = i & 31;
            __nv_bfloat16 v = __float2bfloat16(wa[n*CH*CH + c*CH + d]);
            was[d*40 + c] = *(uint16_t*)&v;
        }
        /* wb: stage-B B operand — K columns in h's PERMUTED order */
        uint16_t* wbs = (uint16_t*)(smc + SM_WB);
        for (int i = tid; i < 9*CH*CH; i += 256) {
            int t = i >> 10, r = i & 1023;
            int d = r >> 5, c = r & 31;
            __nv_bfloat16 v = __float2bfloat16(wb[(size_t)n*9*CH*CH + t*CH*CH + c*CH + d]);
            wbs[t*1280 + d*40 + hpos(c)] = *(uint16_t*)&v;
        }
    }
    if (tid < CH) {
        ((float*)(smc + SM_BA))[tid] = ba[n*CH + tid];
        ((float*)(smc + SM_BB))[tid] = bb[n*CH + tid];
        float s = 0.f;
        const float* wpp = Wp + (n*CH + tid)*CH;
#pragma unroll
        for (int o = 0; o < CH; o++) s += wpp[o];
        ((float*)(smc + SM_WP))[tid] = s;
    }
    cp_wait_all();
    __syncthreads();

    uint32_t aoffA  = (uint32_t)(lane & 15) * RSTRIDE + (uint32_t)(lane >> 4) * 16;
    uint32_t aoffB4 = (uint32_t)(lane & 7)  * RSTRIDE + (uint32_t)(lane >> 3) * 16;

    /* ---- stage A: h = relu(f @ wa + ba), in-place, permuted layout ---- */
    {
        uint32_t bwa[16];
#pragma unroll
        for (int nb = 0; nb < 4; nb++)
            ldsm_x4(bwa + nb*4, sb + SM_WA + nb*8*RSTRIDE + aoffB4);
        float ba_r[8];
        const float* ba_s = (const float*)(smc + SM_BA);
#pragma unroll
        for (int nb = 0; nb < 4; nb++) {
            ba_r[nb*2+0] = ba_s[nb*8 + qid*2 + 0];
            ba_r[nb*2+1] = ba_s[nb*8 + qid*2 + 1];
        }

        for (int st = wid; st < NST_A; st += 8) {
            int P = st * 16;
            uint32_t abase = sb + SM_FH + (uint32_t)(P+1)*RSTRIDE;
            uint32_t A0[4], A1[4];
            ldsm_x4(A0, abase + aoffA);
            ldsm_x4(A1, abase + 32 + aoffA);

            float acc[16];
#pragma unroll
            for (int i = 0; i < 16; i++) acc[i] = 0.f;
#pragma unroll
            for (int nb = 0; nb < 4; nb++) {
                mma16816(acc + nb*4, A0, bwa + nb*4);
                mma16816(acc + nb*4, A1, bwa + nb*4 + 2);
            }

            int p0 = P + row4, p1 = p0 + 8;
            int px0 = p0 % PW, py0 = y0p + p0 / PW;
            int px1 = p1 % PW, py1 = y0p + p1 / PW;
            bool v0 = (p0 < HALON) && (px0 >= 1) && (px0 <= WW) && (py0 >= 1) && (py0 <= HH);
            bool v1 = (p1 < HALON) && (px1 >= 1) && (px1 <= WW) && (py1 >= 1) && (py1 <= HH);

            uint4 q0, q1;
            q0.x = pk_bf16x2(v0 ? fmaxf(acc[0]  + ba_r[0], 0.f) : 0.f,
                             v0 ? fmaxf(acc[1]  + ba_r[1], 0.f) : 0.f);
            q0.y = pk_bf16x2(v0 ? fmaxf(acc[4]  + ba_r[2], 0.f) : 0.f,
                             v0 ? fmaxf(acc[5]  + ba_r[3], 0.f) : 0.f);
            q0.z = pk_bf16x2(v0 ? fmaxf(acc[8]  + ba_r[4], 0.f) : 0.f,
                             v0 ? fmaxf(acc[9]  + ba_r[5], 0.f) : 0.f);
            q0.w = pk_bf16x2(v0 ? fmaxf(acc[12] + ba_r[6], 0.f) : 0.f,
                             v0 ? fmaxf(acc[13] + ba_r[7], 0.f) : 0.f);
            q1.x = pk_bf16x2(v1 ? fmaxf(acc[2]  + ba_r[0], 0.f) : 0.f,
                             v1 ? fmaxf(acc[3]  + ba_r[1], 0.f) : 0.f);
            q1.y = pk_bf16x2(v1 ? fmaxf(acc[6]  + ba_r[2], 0.f) : 0.f,
                             v1 ? fmaxf(acc[7]  + ba_r[3], 0.f) : 0.f);
            q1.z = pk_bf16x2(v1 ? fmaxf(acc[10] + ba_r[4], 0.f) : 0.f,
                             v1 ? fmaxf(acc[11] + ba_r[5], 0.f) : 0.f);
            q1.w = pk_bf16x2(v1 ? fmaxf(acc[14] + ba_r[6], 0.f) : 0.f,
                             v1 ? fmaxf(acc[15] + ba_r[7], 0.f) : 0.f);
            *(uint4*)(smc + SM_FH + (p0+1)*RSTRIDE + qid*16) = q0;
            *(uint4*)(smc + SM_FH + (p1+1)*RSTRIDE + qid*16) = q1;
        }
    }
    __syncthreads();

    /* ---- stage B: 2 passes x (taps unrolled, 3 strips, A double-buffer) ---- */
    {
#pragma unroll 1
        for (int g = 0; g < 2; g++) {
            float acc[3][16];
#pragma unroll
            for (int k = 0; k < 3; k++)
#pragma unroll
                for (int i = 0; i < 16; i++) acc[k][i] = 0.f;

            float fpre[3][2];
#pragma unroll
            for (int k = 0; k < 3; k++) {
                int P = PW + (wid + g*8 + k*16) * 16;
                int p0 = P + row4, p1 = p0 + 8;
                int hx0 = p0 % PW, hy0 = p0 / PW;
                int hx1 = p1 % PW, hy1 = p1 / PW;
                fpre[k][0] = (hx0 >= 1 && hx0 <= WW)
                    ? g_fsum[(b*HH + (y0p + hy0 - 1))*WW + (hx0 - 1)] : 0.f;
                fpre[k][1] = (hx1 >= 1 && hx1 <= WW)
                    ? g_fsum[(b*HH + (y0p + hy1 - 1))*WW + (hx1 - 1)] : 0.f;
            }

            uint32_t Abuf[2][8];
            {
                int P = PW + (wid + g*8) * 16;
                uint32_t abase = sb + SM_FH + (uint32_t)(P - PW - 1 + 1)*RSTRIDE;
                ldsm_x4(Abuf[0],     abase + aoffA);
                ldsm_x4(Abuf[0] + 4, abase + 32 + aoffA);
            }

#pragma unroll
            for (int tap = 0; tap < 9; tap++) {
                uint32_t wbase = sb + SM_WB + tap*2560;
                uint32_t bw[16];
#pragma unroll
                for (int nb = 0; nb < 4; nb++)
                    ldsm_x4(bw + nb*4, wbase + nb*8*RSTRIDE + aoffB4);

#pragma unroll
                for (int k = 0; k < 3; k++) {
                    const int cur = (tap*3 + k) & 1;
                    if (!(tap == 8 && k == 2)) {
                        const int ntap = (k < 2) ? tap : tap + 1;
                        const int nk   = (k < 2) ? k + 1 : 0;
                        const int ns = (ntap/3 - 1)*PW + (ntap%3 - 1);
                        int P = PW + (wid + g*8 + nk*16) * 16;
                        uint32_t abase = sb + SM_FH + (uint32_t)(P + ns + 1)*RSTRIDE;
                        ldsm_x4(Abuf[cur ^ 1],     abase + aoffA);
                        ldsm_x4(Abuf[cur ^ 1] + 4, abase + 32 + aoffA);
                    }
#pragma unroll
                    for (int nb = 0; nb < 4; nb++) {
                        mma16816(acc[k] + nb*4, Abuf[cur],     bw + nb*4);
                        mma16816(acc[k] + nb*4, Abuf[cur] + 4, bw + nb*4 + 2);
                    }
                }
            }

            float bb_r[8], wp_r[8];
            const float* bb_s = (const float*)(smc + SM_BB);
            const float* wp_s = (const float*)(smc + SM_WP);
#pragma unroll
            for (int nb = 0; nb < 4; nb++) {
                bb_r[nb*2+0] = bb_s[nb*8 + qid*2 + 0];
                bb_r[nb*2+1] = bb_s[nb*8 + qid*2 + 1];
                wp_r[nb*2+0] = wp_s[nb*8 + qid*2 + 0];
                wp_r[nb*2+1] = wp_s[nb*8 + qid*2 + 1];
            }

#pragma unroll
            for (int k = 0; k < 3; k++) {
                int P = PW + (wid + g*8 + k*16) * 16;
                float l0 = 0.f, l1 = 0.f;
#pragma unroll
                for (int nb = 0; nb < 4; nb++) {
                    l0 += fmaxf(acc[k][nb*4+0] + bb_r[nb*2+0], 0.f) * wp_r[nb*2+0];
                    l0 += fmaxf(acc[k][nb*4+1] + bb_r[nb*2+1], 0.f) * wp_r[nb*2+1];
                    l1 += fmaxf(acc[k][nb*4+2] + bb_r[nb*2+0], 0.f) * wp_r[nb*2+0];
                    l1 += fmaxf(acc[k][nb*4+3] + bb_r[nb*2+1], 0.f) * wp_r[nb*2+1];
                }
                l0 += __shfl_xor_sync(0xffffffffu, l0, 1);
                l0 += __shfl_xor_sync(0xffffffffu, l0, 2);
                l1 += __shfl_xor_sync(0xffffffffu, l1, 1);
                l1 += __shfl_xor_sync(0xffffffffu, l1, 2);

                if (qid == 0) {
                    int p0 = P + row4;
                    int hx0 = p0 % PW, hy0 = p0 / PW;
                    if (hx0 >= 1 && hx0 <= WW) {
                        int idx = (b*HH + (y0p + hy0 - 1))*WW + (hx0 - 1);
                        scr[idx] = fpre[k][0] + l0;   /* coalesced: 8 lanes, 8 consecutive px */
                    }
                    int p1 = p0 + 8;
                    int hx1 = p1 % PW, hy1 = p1 / PW;
                    if (hx1 >= 1 && hx1 <= WW) {
                        int idx = (b*HH + (y0p + hy1 - 1))*WW + (hx1 - 1);
                        scr[idx] = fpre[k][1] + l1;
                    }
                }
            }
        }

        /* leftover strip 48 (warp 0 only) */
        if (wid == 0) {
            float bb_r[8], wp_r[8];
            const float* bb_s = (const float*)(smc + SM_BB);
            const float* wp_s = (const float*)(smc + SM_WP);
#pragma unroll
            for (int nb = 0; nb < 4; nb++) {
                bb_r[nb*2+0] = bb_s[nb*8 + qid*2 + 0];
                bb_r[nb*2+1] = bb_s[nb*8 + qid*2 + 1];
                wp_r[nb*2+0] = wp_s[nb*8 + qid*2 + 0];
                wp_r[nb*2+1] = wp_s[nb*8 + qid*2 + 1];
            }
            int P = PW + 48 * 16;
            float a4[16];
#pragma unroll
            for (int i = 0; i < 16; i++) a4[i] = 0.f;
#pragma unroll 1
            for (int tap = 0; tap < 9; tap++) {
                int s = (tap/3 - 1)*PW + (tap%3 - 1);
                uint32_t wbase = sb + SM_WB + tap*2560;
                uint32_t abase = sb + SM_FH + (uint32_t)(P + s + 1)*RSTRIDE;
                uint32_t A0[4], A1[4];
                ldsm_x4(A0, abase + aoffA);
                ldsm_x4(A1, abase + 32 + aoffA);
#pragma unroll
                for (int nb = 0; nb < 4; nb++) {
                    uint32_t bw4[4];
                    ldsm_x4(bw4, wbase + nb*8*RSTRIDE + aoffB4);
                    mma16816(a4 + nb*4, A0, bw4);
                    mma16816(a4 + nb*4, A1, bw4 + 2);
                }
            }
            float l0 = 0.f, l1 = 0.f;
#pragma unroll
            for (int nb = 0; nb < 4; nb++) {
                l0 += fmaxf(a4[nb*4+0] + bb_r[nb*2+0], 0.f) * wp_r[nb*2+0];
                l0 += fmaxf(a4[nb*4+1] + bb_r[nb*2+1], 0.f) * wp_r[nb*2+1];
                l1 += fmaxf(a4[nb*4+2] + bb_r[nb*2+0], 0.f) * wp_r[nb*2+0];
                l1 += fmaxf(a4[nb*4+3] + bb_r[nb*2+1], 0.f) * wp_r[nb*2+1];
            }
            l0 += __shfl_xor_sync(0xffffffffu, l0, 1);
            l0 += __shfl_xor_sync(0xffffffffu, l0, 2);
            l1 += __shfl_xor_sync(0xffffffffu, l1, 1);
            l1 += __shfl_xor_sync(0xffffffffu, l1, 2);
            if (qid == 0) {
                int p0 = P + row4;
                int hx0 = p0 % PW, hy0 = p0 / PW;
                if (hx0 >= 1 && hx0 <= WW) {
                    int idx = (b*HH + (y0p + hy0 - 1))*WW + (hx0 - 1);
                    scr[idx] = g_fsum[idx] + l0;
                }
                int p1 = p0 + 8;
                int hx1 = p1 % PW, hy1 = p1 / PW;
                if (hx1 >= 1 && hx1 <= WW) {
                    int idx = (b*HH + (y0p + hy1 - 1))*WW + (hx1 - 1);
                    scr[idx] = g_fsum[idx] + l1;
                }
            }
        }
    }
}

/* ------------------------------------------------------------------ */
/* Kernel 3: transpose scratch [21][B*HW] -> out [B*HW][21]            */
/* ------------------------------------------------------------------ */
__global__ void __launch_bounds__(256)
k3_t(float* __restrict__ out)
{
    __shared__ float t[128*NKP];
    int base = blockIdx.x * 128;
    int tid = threadIdx.x;
    for (int i = tid; i < 128*NKP; i += 256) {
        int n = i >> 7, p = i & 127;
        t[p*NKP + n] = g_scratch[(size_t)n*(BB_*HWPIX) + base + p];
    }
    __syncthreads();
    float* dst = out + (size_t)base*NKP;
    for (int i = tid; i < 128*NKP; i += 256) dst[i] = t[i];
}

/* ------------------------------------------------------------------ */
extern "C" void kernel_launch(void* const* d_in, const int* in_sizes, int n_in,
                              void* d_out, int out_size)
{
    const float* x  = (const float*)d_in[0];
    const float* w2 = (const float*)d_in[1];
    const float* b2 = (const float*)d_in[2];
    const float* wa = (const float*)d_in[3];
    const float* ba = (const float*)d_in[4];
    const float* wb = (const float*)d_in[5];
    const float* bb = (const float*)d_in[6];
    const float* Wp = (const float*)d_in[7];
    float* out = (float*)d_out;

    k1_f<<<(BB_*PPIX + 255)/256, 256>>>(x, w2, b2);

    cudaFuncSetAttribute(k2_main, cudaFuncAttributeMaxDynamicSharedMemorySize, SMEM_SZ);
    dim3 grid(HH/SLABH, NKP*BB_);
    k2_main<<<grid, 256, SMEM_SZ>>>(wa, ba, wb, bb, Wp);

    k3_t<<<(BB_*HWPIX)/128, 256>>>(out);
}